// round 1
// baseline (speedup 1.0000x reference)
#include <cuda_runtime.h>
#include <cuda_bf16.h>

// LinearPositionInterpolation:
//   index: (n,) int32 sorted keypoints (n=129, spacing 32 → m=4096)
//   value: (batch, n, dim) float32   (batch=32, dim=256)
//   out:   (batch, m, dim) float32, rows p=1..m (excludes start point)
//
// Strategy: one block per (batch, segment). Each thread owns dim/4 float4
// lanes, loads y0/y1 ONCE into registers, then sweeps the segment's rows
// writing y0 + (y1-y0)*w. Reads shrink to ~8 MB; kernel is bound by the
// 134 MB output write stream.

static constexpr int DIM  = 256;      // per metadata
static constexpr int DIM4 = DIM / 4;  // 64 float4 lanes

__global__ __launch_bounds__(DIM4, 32)
void lpi_kernel(const int* __restrict__ index,
                const float4* __restrict__ value,
                float4* __restrict__ out,
                int n, int m)
{
    const int nseg = n - 1;
    const int seg  = blockIdx.x % nseg;
    const int b    = blockIdx.x / nseg;
    const int d    = threadIdx.x;            // 0..DIM4-1

    const int base = index[0];
    const int x0   = index[seg]     - base;  // L2-hot after first touch
    const int x1   = index[seg + 1] - base;
    const int len  = x1 - x0;                // #output rows for this segment
    const float inv = 1.0f / (float)len;

    const float4* v = value + ((long long)b * n + seg) * DIM4 + d;
    const float4 y0 = v[0];
    const float4 y1 = v[DIM4];
    const float4 dy = make_float4(y1.x - y0.x, y1.y - y0.y,
                                  y1.z - y0.z, y1.w - y0.w);

    // output row for p = x0 + pc  is (x0 + pc - 1)  (0-based, p starts at 1)
    float4* o = out + ((long long)b * m + x0) * DIM4 + d;

    #pragma unroll 4
    for (int pc = 1; pc <= len; pc++) {
        const float w = (float)pc * inv;
        float4 r;
        r.x = fmaf(dy.x, w, y0.x);
        r.y = fmaf(dy.y, w, y0.y);
        r.z = fmaf(dy.z, w, y0.z);
        r.w = fmaf(dy.w, w, y0.w);
        o[(long long)(pc - 1) * DIM4] = r;
    }
}

extern "C" void kernel_launch(void* const* d_in, const int* in_sizes, int n_in,
                              void* d_out, int out_size)
{
    const int*    index = (const int*)d_in[0];
    const float4* value = (const float4*)d_in[1];
    float4*       out   = (float4*)d_out;

    const int n     = in_sizes[0];                 // 129
    const int batch = in_sizes[1] / (n * DIM);     // 32
    const int m     = out_size / (batch * DIM);    // 4096

    const int nseg = n - 1;
    dim3 grid(batch * nseg);
    dim3 block(DIM4);
    lpi_kernel<<<grid, block>>>(index, value, out, n, m);
}

// round 2
// speedup vs baseline: 1.1146x; 1.1146x over previous
#include <cuda_runtime.h>
#include <cuda_bf16.h>

// LinearPositionInterpolation:
//   index: (n,) int32 sorted keypoints (n=129, spacing 32 -> m=4096)
//   value: (batch, n, dim) float32   (batch=32, dim=256)
//   out:   (batch, m, dim) float32, rows p=1..m (excludes start point)
//
// R2: one block per (batch, segment), 256 threads = 4 row-lanes x 64 dim-lanes.
// Each thread loads y0/y1 once, then issues ~len/4 INDEPENDENT streaming
// stores (__stcs). Goal: raise store MLP per scheduler so the 134 MB output
// write stream saturates DRAM instead of stalling on issue.

static constexpr int DIM   = 256;      // per metadata
static constexpr int DIM4  = DIM / 4;  // 64 float4 lanes per row
static constexpr int RLANE = 4;        // rows in flight per block
static constexpr int TPB   = DIM4 * RLANE;  // 256

__global__ __launch_bounds__(TPB, 8)
void lpi_kernel(const int* __restrict__ index,
                const float4* __restrict__ value,
                float4* __restrict__ out,
                int n, int m)
{
    const int nseg = n - 1;
    const int seg  = blockIdx.x % nseg;
    const int b    = blockIdx.x / nseg;
    const int d    = threadIdx.x & (DIM4 - 1);   // dim lane 0..63
    const int rl   = threadIdx.x >> 6;           // row lane 0..3

    const int base = index[0];
    const int x0   = index[seg]     - base;      // L2-hot
    const int x1   = index[seg + 1] - base;
    const int len  = x1 - x0;                    // rows in this segment
    const float inv = 1.0f / (float)len;

    const float4* v = value + ((long long)b * n + seg) * DIM4 + d;
    const float4 y0 = __ldg(v);
    const float4 y1 = __ldg(v + DIM4);
    const float4 dy = make_float4(y1.x - y0.x, y1.y - y0.y,
                                  y1.z - y0.z, y1.w - y0.w);

    // output row for p = x0 + pc is (x0 + pc - 1) (0-based, p starts at 1)
    float4* o = out + ((long long)(b * m + x0) + rl) * DIM4 + d;
    const long long ostep = (long long)RLANE * DIM4;

    // pc = 1 + rl, 1 + rl + 4, ... ; all iterations independent
    #pragma unroll 4
    for (int pc = 1 + rl; pc <= len; pc += RLANE) {
        const float w = (float)pc * inv;
        float4 r;
        r.x = fmaf(dy.x, w, y0.x);
        r.y = fmaf(dy.y, w, y0.y);
        r.z = fmaf(dy.z, w, y0.z);
        r.w = fmaf(dy.w, w, y0.w);
        __stcs(o, r);                 // streaming store: evict-first
        o += ostep;
    }
}

extern "C" void kernel_launch(void* const* d_in, const int* in_sizes, int n_in,
                              void* d_out, int out_size)
{
    const int*    index = (const int*)d_in[0];
    const float4* value = (const float4*)d_in[1];
    float4*       out   = (float4*)d_out;

    const int n     = in_sizes[0];                 // 129
    const int batch = in_sizes[1] / (n * DIM);     // 32
    const int m     = out_size / (batch * DIM);    // 4096

    const int nseg = n - 1;
    dim3 grid(batch * nseg);                       // 4096 blocks
    dim3 block(TPB);                               // 256 threads
    lpi_kernel<<<grid, block>>>(index, value, out, n, m);
}